// round 4
// baseline (speedup 1.0000x reference)
#include <cuda_runtime.h>
#include <math.h>

#define NB   16
#define NC   2
#define NS   2
#define NF   257
#define NFFT 512
#define NHALF 256
#define HOP  128
#define PADN 256
#define NFRM 2501
#define NT   320000

#define YT_N ((size_t)NB * NS * NC * NT)          // 20,480,000 floats (y_time)
#define YB_E ((size_t)NB * NS * NF * NFRM)        // 20,568,224 complex elements
#define YB_N (YB_E * 2)                           // 41,136,448 floats (re+im)

// ---------------- device scratch (static globals: allocation-free) ----------------
__device__ float2 g_Y[(size_t)NB * NS * NFRM * NF];          // beamformed STFT [b][s][t][f]
__device__ float2 g_frames2[(size_t)NB * NS * NFRM * NHALF]; // windowed irfft frames, float2 pairs
__device__ float2 g_wc[NS * NF * NC];                        // conj(w)
__device__ float  g_win[NFFT];
__device__ float  g_win2[NFFT];
__device__ float2 g_tw[NHALF];                               // e^{-2*pi*i*k/512}

// ---------------- init: window, twiddles, weights ----------------
__global__ void k_init(const float* __restrict__ sr, const float* __restrict__ si) {
    int tid = threadIdx.x;  // 512 threads
    {
        double ang = 2.0 * M_PI * (double)tid / 512.0;
        float w = (float)(0.5 - 0.5 * cos(ang));
        g_win[tid] = w;
        g_win2[tid] = w * w;
    }
    if (tid < NHALF) {
        double ang = -2.0 * M_PI * (double)tid / 512.0;
        double s, c;
        sincos(ang, &s, &c);
        g_tw[tid] = make_float2((float)c, (float)s);
    }
    for (int i = tid; i < NS * NF; i += 512) {
        int base = i * 2;
        float a0r = sr[base], a0i = si[base];
        float a1r = sr[base + 1], a1i = si[base + 1];
        float den = a0r * a0r + a0i * a0i + a1r * a1r + a1i * a1i;
        float inv = 1.0f / den;
        g_wc[base]     = make_float2(a0r * inv, -a0i * inv);
        g_wc[base + 1] = make_float2(a1r * inv, -a1i * inv);
    }
}

__device__ __forceinline__ int reflect_idx(int i) {
    i = (i < 0) ? -i : i;
    return (i >= NT) ? (2 * NT - 2 - i) : i;
}

// ---------------- STFT (both channels) + beamform, one block per (b, frame) ----------------
__global__ __launch_bounds__(256) void k_stft(const float* __restrict__ x) {
    int bt = blockIdx.x;
    int b = bt / NFRM, t = bt - b * NFRM;
    int tid = threadIdx.x;
    int c = tid >> 7, j = tid & 127;

    __shared__ float2 s_tw[NHALF];
    __shared__ float2 buf[2][2][NHALF];
    __shared__ float2 sX[2][NF];

    s_tw[tid] = g_tw[tid];

    const float* xin = x + (size_t)(b * NC + c) * NT;
    int base = t * HOP - PADN;
#pragma unroll
    for (int kk = 0; kk < 2; kk++) {
        int k = j + kk * 128;
        int i0 = base + 2 * k;
        float v0 = xin[reflect_idx(i0)]     * g_win[2 * k];
        float v1 = xin[reflect_idx(i0 + 1)] * g_win[2 * k + 1];
        buf[c][0][k] = make_float2(v0, v1);
    }
    __syncthreads();

    // 256-pt Stockham FFT (forward)
    int p = 0;
#pragma unroll
    for (int st = 0; st < 8; st++) {
        int Ns = 1 << st;
        float2 a  = buf[c][p][j];
        float2 bv = buf[c][p][j + 128];
        float2 w  = s_tw[(j & (Ns - 1)) << (8 - st)];
        float2 bw = make_float2(bv.x * w.x - bv.y * w.y, bv.x * w.y + bv.y * w.x);
        int d = ((j >> st) << (st + 1)) + (j & (Ns - 1));
        buf[c][p ^ 1][d]      = make_float2(a.x + bw.x, a.y + bw.y);
        buf[c][p ^ 1][d + Ns] = make_float2(a.x - bw.x, a.y - bw.y);
        p ^= 1;
        __syncthreads();
    }

    // unpack 256-pt complex FFT -> 512-pt rfft bins
#pragma unroll
    for (int kk = 0; kk < 2; kk++) {
        int k = j + kk * 128;
        float2 Zk = buf[c][p][k];
        float2 Zm = buf[c][p][(256 - k) & 255];
        float Ex = 0.5f * (Zk.x + Zm.x), Ey = 0.5f * (Zk.y - Zm.y);
        float Dx = 0.5f * (Zk.x - Zm.x), Dy = 0.5f * (Zk.y + Zm.y);
        float Ox = Dy, Oy = -Dx;  // -i * D
        float2 w = s_tw[k];
        float OWx = Ox * w.x - Oy * w.y;
        float OWy = Ox * w.y + Oy * w.x;
        sX[c][k] = make_float2(Ex + OWx, Ey + OWy);
    }
    if (j == 0) {
        float2 Z0 = buf[c][p][0];
        sX[c][256] = make_float2(Z0.x - Z0.y, 0.0f);
    }
    __syncthreads();

    // beamform: Y[s][k] = sum_c conjw[s][k][c] * X[c][k]; write [b][s][t][f]
    float2* Yout = g_Y + ((size_t)(b * NS) * NFRM + t) * NF;
    for (int item = tid; item < NS * NF; item += 256) {
        int s = (item >= NF);
        int k = item - s * NF;
        float2 w0 = g_wc[(s * NF + k) * 2];
        float2 w1 = g_wc[(s * NF + k) * 2 + 1];
        float2 X0 = sX[0][k], X1 = sX[1][k];
        float yr = w0.x * X0.x - w0.y * X0.y + w1.x * X1.x - w1.y * X1.y;
        float yi = w0.x * X0.y + w0.y * X0.x + w1.x * X1.y + w1.y * X1.x;
        Yout[(size_t)s * NFRM * NF + k] = make_float2(yr, yi);
    }
}

// ---------------- transpose Y [t][f] -> planar/real output [f][t] per (b,s) ----------------
// reOut: real plane base; imOut: imag plane base (may be null -> real-only mode)
__global__ void k_transpose(float* __restrict__ reOut, float* __restrict__ imOut,
                            unsigned long long planeCap) {
    __shared__ float2 tile[32][33];
    int bs = blockIdx.z;
    int f0 = blockIdx.x << 5, t0 = blockIdx.y << 5;
    const float2* src = g_Y + (size_t)bs * NFRM * NF;
#pragma unroll
    for (int i = 0; i < 4; i++) {
        int tt = t0 + threadIdx.y + i * 8, ff = f0 + threadIdx.x;
        if (tt < NFRM && ff < NF)
            tile[threadIdx.y + i * 8][threadIdx.x] = src[(size_t)tt * NF + ff];
    }
    __syncthreads();
    size_t dbase = (size_t)bs * NF * NFRM;
#pragma unroll
    for (int i = 0; i < 4; i++) {
        int ff = f0 + threadIdx.y + i * 8, tt = t0 + threadIdx.x;
        if (ff < NF && tt < NFRM) {
            size_t di = dbase + (size_t)ff * NFRM + tt;
            if (di < planeCap) {
                float2 v = tile[threadIdx.x][threadIdx.y + i * 8];
                reOut[di] = v.x;
                if (imOut) imOut[di] = v.y;
            }
        }
    }
}

// ---------------- inverse rfft + window per frame ----------------
__global__ __launch_bounds__(256) void k_istft() {
    int bt = blockIdx.x;
    int b = bt / NFRM, t = bt - b * NFRM;
    int tid = threadIdx.x;
    int s = tid >> 7, j = tid & 127;

    __shared__ float2 s_tw[NHALF];
    __shared__ float2 buf[2][2][NHALF];
    __shared__ float2 sX[2][NF];

    s_tw[tid] = g_tw[tid];

    const float2* Yin = g_Y + ((size_t)(b * NS + s) * NFRM + t) * NF;
    sX[s][j] = Yin[j];
    sX[s][j + 128] = Yin[j + 128];
    if (j == 0) {
        // irfft ignores imag of bins 0 and N/2
        float2 y0 = Yin[0];
        sX[s][0] = make_float2(y0.x, 0.0f);
        float2 yn = Yin[256];
        sX[s][256] = make_float2(yn.x, 0.0f);
    }
    __syncthreads();

#pragma unroll
    for (int kk = 0; kk < 2; kk++) {
        int k = j + kk * 128;
        float2 Xk = sX[s][k];
        float2 Xm = sX[s][256 - k];
        float Ex = 0.5f * (Xk.x + Xm.x), Ey = 0.5f * (Xk.y - Xm.y);
        float Dx = 0.5f * (Xk.x - Xm.x), Dy = 0.5f * (Xk.y + Xm.y);
        float2 w = s_tw[k];
        float Ox = Dx * w.x + Dy * w.y;   // D * conj(w)
        float Oy = Dy * w.x - Dx * w.y;
        buf[s][0][k] = make_float2(Ex - Oy, Ey + Ox);  // E + i*O
    }
    __syncthreads();

    int p = 0;
#pragma unroll
    for (int st = 0; st < 8; st++) {
        int Ns = 1 << st;
        float2 a  = buf[s][p][j];
        float2 bv = buf[s][p][j + 128];
        float2 w  = s_tw[(j & (Ns - 1)) << (8 - st)];
        float2 bw = make_float2(bv.x * w.x + bv.y * w.y, bv.y * w.x - bv.x * w.y);
        int d = ((j >> st) << (st + 1)) + (j & (Ns - 1));
        buf[s][p ^ 1][d]      = make_float2(a.x + bw.x, a.y + bw.y);
        buf[s][p ^ 1][d + Ns] = make_float2(a.x - bw.x, a.y - bw.y);
        p ^= 1;
        __syncthreads();
    }

    float2* fout = g_frames2 + ((size_t)(b * NS + s) * NFRM + t) * NHALF;
    const float scale = 1.0f / 256.0f;
#pragma unroll
    for (int kk = 0; kk < 2; kk++) {
        int k = j + kk * 128;
        float2 z = buf[s][p][k];
        fout[k] = make_float2(z.x * scale * g_win[2 * k],
                              z.y * scale * g_win[2 * k + 1]);
    }
}

// ---------------- gather overlap-add + envelope normalize + stereo duplicate ----------------
__global__ void k_combine(float* __restrict__ yt, unsigned long long cap) {
    int idx = blockIdx.x * blockDim.x + threadIdx.x;
    if (idx >= NB * NS * NT) return;
    int bs = idx / NT;
    int mo = idx - bs * NT;
    int m = mo + PADN;
    int klo = m - 384;
    klo = (klo < 0) ? 0 : (klo >> 7);
    int khi = m >> 7;
    if (khi > NFRM - 1) khi = NFRM - 1;
    const float* fr = (const float*)(g_frames2 + (size_t)bs * NFRM * NHALF);
    float y = 0.0f, env = 0.0f;
    for (int k = klo; k <= khi; k++) {
        int r = m - (k << 7);
        y += fr[(size_t)k * NFFT + r];
        env += g_win2[r];
    }
    float v = y / env;
    size_t i0 = (size_t)(bs * 2) * NT + mo;
    size_t i1 = (size_t)(bs * 2 + 1) * NT + mo;
    if (i0 < cap) yt[i0] = v;
    if (i1 < cap) yt[i1] = v;
}

// ---------------- launcher ----------------
extern "C" void kernel_launch(void* const* d_in, const int* in_sizes, int n_in,
                              void* d_out, int out_size) {
    // identify inputs by size: x is the big one; remaining two keep order (sr, si)
    const float* x = 0; const float* small[2] = {0, 0}; int nsmall = 0;
    for (int i = 0; i < n_in && i < 3; i++) {
        if (in_sizes[i] > 1000000) x = (const float*)d_in[i];
        else if (nsmall < 2) small[nsmall++] = (const float*)d_in[i];
    }
    const float* sr = small[0] ? small[0] : (const float*)d_in[1];
    const float* si = small[1] ? small[1] : (const float*)d_in[2];
    if (!x) x = (const float*)d_in[0];

    size_t osz = (size_t)out_size;
    float* base = (float*)d_out;

    float* yt = 0;  unsigned long long ytCap = 0;
    float* re = 0;  float* im = 0;  unsigned long long planeCap = 0;

    if (osz == YT_N + YB_N) {
        // hypothesis P: planar complex serialization (re-plane, then im-plane)
        yt = base;              ytCap = YT_N;
        re = base + YT_N;       im = base + YT_N + YB_E;   planeCap = YB_E;
    } else if (osz == YT_N + YB_E) {
        // hypothesis A: complex64 coerced to float32 (real part only)
        yt = base;              ytCap = YT_N;
        re = base + YT_N;       im = 0;                    planeCap = YB_E;
    } else if (osz == YT_N) {
        yt = base;              ytCap = YT_N;
    } else if (osz == YB_N) {
        re = base;              im = base + YB_E;          planeCap = YB_E;
    } else if (osz == YB_E) {
        re = base;              im = 0;                    planeCap = YB_E;
    } else {
        // unknown: y_time first, then guarded planar remainder
        yt = base;              ytCap = (osz < YT_N) ? osz : YT_N;
        if (osz > YT_N) {
            size_t rem = osz - YT_N;
            re = base + YT_N;
            if (rem >= 2 * YB_E) { im = base + YT_N + YB_E; planeCap = YB_E; }
            else                 { im = 0; planeCap = rem; }
        }
    }

    k_init<<<1, 512>>>(sr, si);
    k_stft<<<NB * NFRM, 256>>>(x);
    if (re) {
        dim3 tg((NF + 31) / 32, (NFRM + 31) / 32, NB * NS);
        k_transpose<<<tg, dim3(32, 8)>>>(re, im, planeCap);
    }
    if (yt) {
        k_istft<<<NB * NFRM, 256>>>();
        k_combine<<<(NB * NS * NT + 255) / 256, 256>>>(yt, ytCap);
    }
}

// round 5
// speedup vs baseline: 1.4078x; 1.4078x over previous
#include <cuda_runtime.h>
#include <math.h>

#define NB   16
#define NC   2
#define NS   2
#define NF   257
#define NFFT 512
#define NHALF 256
#define HOP  128
#define PADN 256
#define NFRM 2501
#define NT   320000

#define YT_N ((size_t)NB * NS * NC * NT)          // 20,480,000 floats (y_time)
#define YB_E ((size_t)NB * NS * NF * NFRM)        // 20,568,224 complex elements
#define YB_N (YB_E * 2)                           // 41,136,448 floats (re+im)

// ---------------- device scratch ----------------
__device__ float2 g_Y[(size_t)NB * NS * NFRM * NF];          // beamformed STFT [b][s][t][f]
__device__ float2 g_frames2[(size_t)NB * NS * NFRM * NHALF]; // windowed irfft frames (pairs)
__device__ float2 g_wc[NS * NF * NC];                        // conj(w)
__device__ float  g_win[NFFT];
__device__ float  g_win2[NFFT];
__device__ float2 g_tw[512];                                 // W_512^k = e^{-2pi i k/512}

__device__ __forceinline__ float2 cadd(float2 a, float2 b) { return make_float2(a.x + b.x, a.y + b.y); }
__device__ __forceinline__ float2 csub(float2 a, float2 b) { return make_float2(a.x - b.x, a.y - b.y); }
__device__ __forceinline__ float2 cmul(float2 a, float2 w) {
    return make_float2(a.x * w.x - a.y * w.y, a.x * w.y + a.y * w.x);
}
__device__ __forceinline__ float2 cmulc(float2 a, float2 w) {  // a * conj(w)
    return make_float2(a.x * w.x + a.y * w.y, a.y * w.x - a.x * w.y);
}

// ---------------- init ----------------
__global__ void k_init(const float* __restrict__ sr, const float* __restrict__ si) {
    int tid = threadIdx.x;  // 512 threads
    {
        double ang = 2.0 * M_PI * (double)tid / 512.0;
        float w = (float)(0.5 - 0.5 * cos(ang));
        g_win[tid] = w;
        g_win2[tid] = w * w;
    }
    {
        double ang = -2.0 * M_PI * (double)tid / 512.0;
        double s, c;
        sincos(ang, &s, &c);
        g_tw[tid] = make_float2((float)c, (float)s);
    }
    for (int i = tid; i < NS * NF; i += 512) {
        int base = i * 2;
        float a0r = sr[base], a0i = si[base];
        float a1r = sr[base + 1], a1i = si[base + 1];
        float den = a0r * a0r + a0i * a0i + a1r * a1r + a1i * a1i;
        float inv = 1.0f / den;
        g_wc[base]     = make_float2(a0r * inv, -a0i * inv);
        g_wc[base + 1] = make_float2(a1r * inv, -a1i * inv);
    }
}

__device__ __forceinline__ int reflect_idx(int i) {
    i = (i < 0) ? -i : i;
    return (i >= NT) ? (2 * NT - 2 - i) : i;
}

// ---------------- STFT (radix-4 Stockham) + beamform; 128 thr = 2 ch x 64 ----------------
__global__ __launch_bounds__(128) void k_stft(const float* __restrict__ x) {
    int bt = blockIdx.x;
    int b = bt / NFRM, t = bt - b * NFRM;
    int tid = threadIdx.x;
    int c = tid >> 6, j = tid & 63;

    __shared__ float2 s_tw[512];
    __shared__ float2 buf[2][2][NHALF];
    __shared__ float2 sX[2][NF];

#pragma unroll
    for (int i = 0; i < 4; i++) s_tw[tid + 128 * i] = g_tw[tid + 128 * i];

    const float* xin = x + (size_t)(b * NC + c) * NT;
    int base = t * HOP - PADN;

    float2 v[4];
    if (t >= 2 && t <= 2498) {  // interior: aligned float2 fast path
        const float2* x2 = (const float2*)(xin + base);
#pragma unroll
        for (int q = 0; q < 4; q++) {
            int k = j + 64 * q;
            float2 xx = x2[k];
            v[q] = make_float2(xx.x * g_win[2 * k], xx.y * g_win[2 * k + 1]);
        }
    } else {
#pragma unroll
        for (int q = 0; q < 4; q++) {
            int k = j + 64 * q;
            int i0 = base + 2 * k;
            v[q] = make_float2(xin[reflect_idx(i0)] * g_win[2 * k],
                               xin[reflect_idx(i0 + 1)] * g_win[2 * k + 1]);
        }
    }

    // stage 0 (Ns=1, twiddles=1), input in registers, forward (-i)
    {
        float2 s0 = cadd(v[0], v[2]), d0 = csub(v[0], v[2]);
        float2 s1 = cadd(v[1], v[3]), d1 = csub(v[1], v[3]);
        buf[c][0][4 * j + 0] = cadd(s0, s1);
        buf[c][0][4 * j + 1] = make_float2(d0.x + d1.y, d0.y - d1.x);  // d0 - i d1
        buf[c][0][4 * j + 2] = csub(s0, s1);
        buf[c][0][4 * j + 3] = make_float2(d0.x - d1.y, d0.y + d1.x);  // d0 + i d1
    }
    __syncthreads();

    int p = 0;
#pragma unroll
    for (int st = 1; st < 4; st++) {
        int Ns = 1 << (2 * st);
        int r = j & (Ns - 1);
        int tb = r << (7 - 2 * st);  // exponent in W_512: q * r * 128/Ns
        float2 a0 = buf[c][p][j];
        float2 a1 = buf[c][p][j + 64];
        float2 a2 = buf[c][p][j + 128];
        float2 a3 = buf[c][p][j + 192];
        a1 = cmul(a1, s_tw[tb]);
        a2 = cmul(a2, s_tw[2 * tb]);
        a3 = cmul(a3, s_tw[3 * tb]);
        float2 s0 = cadd(a0, a2), d0 = csub(a0, a2);
        float2 s1 = cadd(a1, a3), d1 = csub(a1, a3);
        int bse = ((j >> (2 * st)) << (2 * st + 2)) + r;
        buf[c][p ^ 1][bse]          = cadd(s0, s1);
        buf[c][p ^ 1][bse + Ns]     = make_float2(d0.x + d1.y, d0.y - d1.x);
        buf[c][p ^ 1][bse + 2 * Ns] = csub(s0, s1);
        buf[c][p ^ 1][bse + 3 * Ns] = make_float2(d0.x - d1.y, d0.y + d1.x);
        p ^= 1;
        __syncthreads();
    }

    // unpack 256-pt complex -> 512-pt rfft bins
#pragma unroll
    for (int q = 0; q < 4; q++) {
        int k = j + 64 * q;
        float2 Zk = buf[c][p][k];
        float2 Zm = buf[c][p][(256 - k) & 255];
        float Ex = 0.5f * (Zk.x + Zm.x), Ey = 0.5f * (Zk.y - Zm.y);
        float Dx = 0.5f * (Zk.x - Zm.x), Dy = 0.5f * (Zk.y + Zm.y);
        float Ox = Dy, Oy = -Dx;  // -i * D
        float2 w = s_tw[k];
        sX[c][k] = make_float2(Ex + (Ox * w.x - Oy * w.y),
                               Ey + (Ox * w.y + Oy * w.x));
    }
    if (j == 0) {
        float2 Z0 = buf[c][p][0];
        sX[c][256] = make_float2(Z0.x - Z0.y, 0.0f);
    }
    __syncthreads();

    // beamform: Y[s][k] = sum_c conj(w)[s][k][c] * X[c][k]
    float2* Yout = g_Y + ((size_t)(b * NS) * NFRM + t) * NF;
    for (int item = tid; item < NS * NF; item += 128) {
        int s = (item >= NF);
        int k = item - s * NF;
        float2 w0 = g_wc[(s * NF + k) * 2];
        float2 w1 = g_wc[(s * NF + k) * 2 + 1];
        float2 X0 = sX[0][k], X1 = sX[1][k];
        float yr = w0.x * X0.x - w0.y * X0.y + w1.x * X1.x - w1.y * X1.y;
        float yi = w0.x * X0.y + w0.y * X0.x + w1.x * X1.y + w1.y * X1.x;
        Yout[(size_t)s * NFRM * NF + k] = make_float2(yr, yi);
    }
}

// ---------------- transpose Y [t][f] -> planar output [f][t] per (b,s) ----------------
__global__ void k_transpose(float* __restrict__ reOut, float* __restrict__ imOut,
                            unsigned long long planeCap) {
    __shared__ float2 tile[32][33];
    int bs = blockIdx.z;
    int f0 = blockIdx.x << 5, t0 = blockIdx.y << 5;
    const float2* src = g_Y + (size_t)bs * NFRM * NF;
#pragma unroll
    for (int i = 0; i < 4; i++) {
        int tt = t0 + threadIdx.y + i * 8, ff = f0 + threadIdx.x;
        if (tt < NFRM && ff < NF)
            tile[threadIdx.y + i * 8][threadIdx.x] = src[(size_t)tt * NF + ff];
    }
    __syncthreads();
    size_t dbase = (size_t)bs * NF * NFRM;
#pragma unroll
    for (int i = 0; i < 4; i++) {
        int ff = f0 + threadIdx.y + i * 8, tt = t0 + threadIdx.x;
        if (ff < NF && tt < NFRM) {
            size_t di = dbase + (size_t)ff * NFRM + tt;
            if (di < planeCap) {
                float2 v = tile[threadIdx.x][threadIdx.y + i * 8];
                reOut[di] = v.x;
                if (imOut) imOut[di] = v.y;
            }
        }
    }
}

// ---------------- inverse rfft (radix-4) + window; 128 thr = 2 steer x 64 ----------------
__global__ __launch_bounds__(128) void k_istft() {
    int bt = blockIdx.x;
    int b = bt / NFRM, t = bt - b * NFRM;
    int tid = threadIdx.x;
    int s = tid >> 6, j = tid & 63;

    __shared__ float2 s_tw[512];
    __shared__ float2 buf[2][2][NHALF];
    __shared__ float2 sX[2][NF];

#pragma unroll
    for (int i = 0; i < 4; i++) s_tw[tid + 128 * i] = g_tw[tid + 128 * i];

    const float2* Yin = g_Y + ((size_t)(b * NS + s) * NFRM + t) * NF;
#pragma unroll
    for (int q = 0; q < 4; q++) sX[s][j + 64 * q] = Yin[j + 64 * q];
    if (j == 0) {
        // irfft ignores imag of bins 0 and N/2
        sX[s][0]   = make_float2(Yin[0].x, 0.0f);
        sX[s][256] = make_float2(Yin[256].x, 0.0f);
    }
    __syncthreads();

    // pack -> registers, then stage 0 (inverse, +i) in registers
    float2 z[4];
#pragma unroll
    for (int q = 0; q < 4; q++) {
        int k = j + 64 * q;
        float2 Xk = sX[s][k];
        float2 Xm = sX[s][256 - k];
        float Ex = 0.5f * (Xk.x + Xm.x), Ey = 0.5f * (Xk.y - Xm.y);
        float Dx = 0.5f * (Xk.x - Xm.x), Dy = 0.5f * (Xk.y + Xm.y);
        float2 w = s_tw[k];
        float Ox = Dx * w.x + Dy * w.y;   // D * conj(w)
        float Oy = Dy * w.x - Dx * w.y;
        z[q] = make_float2(Ex - Oy, Ey + Ox);  // E + i*O
    }
    {
        float2 s0 = cadd(z[0], z[2]), d0 = csub(z[0], z[2]);
        float2 s1 = cadd(z[1], z[3]), d1 = csub(z[1], z[3]);
        buf[s][0][4 * j + 0] = cadd(s0, s1);
        buf[s][0][4 * j + 1] = make_float2(d0.x - d1.y, d0.y + d1.x);  // d0 + i d1
        buf[s][0][4 * j + 2] = csub(s0, s1);
        buf[s][0][4 * j + 3] = make_float2(d0.x + d1.y, d0.y - d1.x);  // d0 - i d1
    }
    __syncthreads();

    int p = 0;
#pragma unroll
    for (int st = 1; st < 3; st++) {
        int Ns = 1 << (2 * st);
        int r = j & (Ns - 1);
        int tb = r << (7 - 2 * st);
        float2 a0 = buf[s][p][j];
        float2 a1 = buf[s][p][j + 64];
        float2 a2 = buf[s][p][j + 128];
        float2 a3 = buf[s][p][j + 192];
        a1 = cmulc(a1, s_tw[tb]);
        a2 = cmulc(a2, s_tw[2 * tb]);
        a3 = cmulc(a3, s_tw[3 * tb]);
        float2 s0 = cadd(a0, a2), d0 = csub(a0, a2);
        float2 s1 = cadd(a1, a3), d1 = csub(a1, a3);
        int bse = ((j >> (2 * st)) << (2 * st + 2)) + r;
        buf[s][p ^ 1][bse]          = cadd(s0, s1);
        buf[s][p ^ 1][bse + Ns]     = make_float2(d0.x - d1.y, d0.y + d1.x);
        buf[s][p ^ 1][bse + 2 * Ns] = csub(s0, s1);
        buf[s][p ^ 1][bse + 3 * Ns] = make_float2(d0.x + d1.y, d0.y - d1.x);
        p ^= 1;
        __syncthreads();
    }

    // stage 3 (Ns=64): outputs land at j + 64p -> write gmem directly
    {
        int tb = j << 1;
        float2 a0 = buf[s][p][j];
        float2 a1 = cmulc(buf[s][p][j + 64],  s_tw[tb]);
        float2 a2 = cmulc(buf[s][p][j + 128], s_tw[2 * tb]);
        float2 a3 = cmulc(buf[s][p][j + 192], s_tw[3 * tb]);
        float2 s0 = cadd(a0, a2), d0 = csub(a0, a2);
        float2 s1 = cadd(a1, a3), d1 = csub(a1, a3);
        float2 c0 = cadd(s0, s1);
        float2 c1 = make_float2(d0.x - d1.y, d0.y + d1.x);
        float2 c2 = csub(s0, s1);
        float2 c3 = make_float2(d0.x + d1.y, d0.y - d1.x);

        float2* fout = g_frames2 + ((size_t)(b * NS + s) * NFRM + t) * NHALF;
        const float sc = 1.0f / 256.0f;
        float2 cc[4] = {c0, c1, c2, c3};
#pragma unroll
        for (int q = 0; q < 4; q++) {
            int k = j + 64 * q;
            fout[k] = make_float2(cc[q].x * sc * g_win[2 * k],
                                  cc[q].y * sc * g_win[2 * k + 1]);
        }
    }
}

// ---------------- overlap-add (vectorized, 2 samples/thread) ----------------
__global__ void k_combine(float* __restrict__ yt, unsigned long long cap) {
    int idx = blockIdx.x * blockDim.x + threadIdx.x;
    const int half = NT / 2;
    if (idx >= NB * NS * half) return;
    int bs = idx / half;
    int mo = (idx - bs * half) * 2;
    int m = mo + PADN;
    int klo = m - 384;
    klo = (klo < 0) ? 0 : (klo >> 7);
    int khi = m >> 7;
    if (khi > NFRM - 1) khi = NFRM - 1;
    const float2* fr2 = g_frames2 + (size_t)bs * NFRM * NHALF;
    float y0 = 0.0f, y1 = 0.0f, e0 = 0.0f, e1 = 0.0f;
    for (int k = klo; k <= khi; k++) {
        int r = m - (k << 7);   // even, <= 510
        float2 v = fr2[(size_t)k * NHALF + (r >> 1)];
        y0 += v.x; y1 += v.y;
        e0 += g_win2[r]; e1 += g_win2[r + 1];
    }
    float2 out = make_float2(y0 / e0, y1 / e1);
    size_t i0 = (size_t)(bs * 2) * NT + mo;
    size_t i1 = (size_t)(bs * 2 + 1) * NT + mo;
    if (i0 + 1 < cap) *(float2*)(yt + i0) = out;
    if (i1 + 1 < cap) *(float2*)(yt + i1) = out;
}

// ---------------- launcher ----------------
extern "C" void kernel_launch(void* const* d_in, const int* in_sizes, int n_in,
                              void* d_out, int out_size) {
    const float* x = 0; const float* small[2] = {0, 0}; int nsmall = 0;
    for (int i = 0; i < n_in && i < 3; i++) {
        if (in_sizes[i] > 1000000) x = (const float*)d_in[i];
        else if (nsmall < 2) small[nsmall++] = (const float*)d_in[i];
    }
    const float* sr = small[0] ? small[0] : (const float*)d_in[1];
    const float* si = small[1] ? small[1] : (const float*)d_in[2];
    if (!x) x = (const float*)d_in[0];

    size_t osz = (size_t)out_size;
    float* base = (float*)d_out;

    float* yt = 0;  unsigned long long ytCap = 0;
    float* re = 0;  float* im = 0;  unsigned long long planeCap = 0;

    if (osz == YT_N + YB_N) {
        yt = base;              ytCap = YT_N;
        re = base + YT_N;       im = base + YT_N + YB_E;   planeCap = YB_E;
    } else if (osz == YT_N + YB_E) {
        yt = base;              ytCap = YT_N;
        re = base + YT_N;       im = 0;                    planeCap = YB_E;
    } else if (osz == YT_N) {
        yt = base;              ytCap = YT_N;
    } else if (osz == YB_N) {
        re = base;              im = base + YB_E;          planeCap = YB_E;
    } else if (osz == YB_E) {
        re = base;              im = 0;                    planeCap = YB_E;
    } else {
        yt = base;              ytCap = (osz < YT_N) ? osz : YT_N;
        if (osz > YT_N) {
            size_t rem = osz - YT_N;
            re = base + YT_N;
            if (rem >= 2 * YB_E) { im = base + YT_N + YB_E; planeCap = YB_E; }
            else                 { im = 0; planeCap = rem; }
        }
    }

    k_init<<<1, 512>>>(sr, si);
    k_stft<<<NB * NFRM, 128>>>(x);
    if (re) {
        dim3 tg((NF + 31) / 32, (NFRM + 31) / 32, NB * NS);
        k_transpose<<<tg, dim3(32, 8)>>>(re, im, planeCap);
    }
    if (yt) {
        k_istft<<<NB * NFRM, 128>>>();
        k_combine<<<(NB * NS * (NT / 2) + 255) / 256, 256>>>(yt, ytCap);
    }
}

// round 6
// speedup vs baseline: 2.0290x; 1.4413x over previous
#include <cuda_runtime.h>
#include <math.h>

#define NB   16
#define NC   2
#define NS   2
#define NF   257
#define NFFT 512
#define NHALF 256
#define HOP  128
#define PADN 256
#define NFRM 2501
#define NT   320000

#define YT_N ((size_t)NB * NS * NC * NT)          // 20,480,000 floats (y_time)
#define YB_E ((size_t)NB * NS * NF * NFRM)        // 20,568,224 complex elements
#define YB_N (YB_E * 2)                           // 41,136,448 floats (re+im)

// bank-conflict swizzle for the FFT smem buffer: flip bits [2:3] with bits [4:5]
#define SWZ(k) ((k) ^ (((k) >> 2) & 12))

#define CW (-0.012271846303085129f)   // -2*pi/512

// ---------------- device scratch ----------------
__device__ float2 g_Y[(size_t)NB * NS * NFRM * NF];          // beamformed STFT [b][s][t][f]
__device__ float2 g_frames2[(size_t)NB * NS * NFRM * NHALF]; // windowed irfft frames (pairs)
__device__ float2 g_wc[NS * NF * NC];                        // conj(w)
__device__ float  g_win[NFFT];
__device__ float  g_win2[NFFT];

__device__ __forceinline__ float2 cadd(float2 a, float2 b) { return make_float2(a.x + b.x, a.y + b.y); }
__device__ __forceinline__ float2 csub(float2 a, float2 b) { return make_float2(a.x - b.x, a.y - b.y); }
__device__ __forceinline__ float2 cmul(float2 a, float2 w) {
    return make_float2(a.x * w.x - a.y * w.y, a.x * w.y + a.y * w.x);
}

// ---------------- init ----------------
__global__ void k_init(const float* __restrict__ sr, const float* __restrict__ si) {
    int tid = threadIdx.x;  // 512 threads
    {
        double ang = 2.0 * M_PI * (double)tid / 512.0;
        float w = (float)(0.5 - 0.5 * cos(ang));
        g_win[tid] = w;
        g_win2[tid] = w * w;
    }
    for (int i = tid; i < NS * NF; i += 512) {
        int base = i * 2;
        float a0r = sr[base], a0i = si[base];
        float a1r = sr[base + 1], a1i = si[base + 1];
        float den = a0r * a0r + a0i * a0i + a1r * a1r + a1i * a1i;
        float inv = 1.0f / den;
        g_wc[base]     = make_float2(a0r * inv, -a0i * inv);
        g_wc[base + 1] = make_float2(a1r * inv, -a1i * inv);
    }
}

__device__ __forceinline__ int reflect_idx(int i) {
    i = (i < 0) ? -i : i;
    return (i >= NT) ? (2 * NT - 2 - i) : i;
}

// ---------------- STFT (radix-4 Stockham, swizzled smem, sincosf twiddles) ----------------
__global__ __launch_bounds__(128) void k_stft(const float* __restrict__ x) {
    int bt = blockIdx.x;
    int b = bt / NFRM, t = bt - b * NFRM;
    int tid = threadIdx.x;
    int c = tid >> 6, j = tid & 63;

    __shared__ float2 buf[2][2][NHALF];
    __shared__ float2 sX[2][NF];

    const float* xin = x + (size_t)(b * NC + c) * NT;
    int base = t * HOP - PADN;

    float2 v[4];
    if (t >= 2 && t <= 2498) {  // interior: aligned float2 fast path
        const float2* x2 = (const float2*)(xin + base);
#pragma unroll
        for (int q = 0; q < 4; q++) {
            int k = j + 64 * q;
            float2 xx = x2[k];
            v[q] = make_float2(xx.x * g_win[2 * k], xx.y * g_win[2 * k + 1]);
        }
    } else {
#pragma unroll
        for (int q = 0; q < 4; q++) {
            int k = j + 64 * q;
            int i0 = base + 2 * k;
            v[q] = make_float2(xin[reflect_idx(i0)] * g_win[2 * k],
                               xin[reflect_idx(i0 + 1)] * g_win[2 * k + 1]);
        }
    }

    // stage 0 (Ns=1), forward (-i)
    {
        float2 s0 = cadd(v[0], v[2]), d0 = csub(v[0], v[2]);
        float2 s1 = cadd(v[1], v[3]), d1 = csub(v[1], v[3]);
        buf[c][0][SWZ(4 * j + 0)] = cadd(s0, s1);
        buf[c][0][SWZ(4 * j + 1)] = make_float2(d0.x + d1.y, d0.y - d1.x);  // d0 - i d1
        buf[c][0][SWZ(4 * j + 2)] = csub(s0, s1);
        buf[c][0][SWZ(4 * j + 3)] = make_float2(d0.x - d1.y, d0.y + d1.x);  // d0 + i d1
    }
    __syncthreads();

    int p = 0;
#pragma unroll
    for (int st = 1; st < 4; st++) {
        int Ns = 1 << (2 * st);
        int r = j & (Ns - 1);
        int tb = r << (7 - 2 * st);  // exponent in W_512
        float sn, cs;
        __sincosf(CW * (float)tb, &sn, &cs);
        float2 w1 = make_float2(cs, sn);
        float2 w2 = cmul(w1, w1);
        float2 w3 = cmul(w2, w1);
        float2 a0 = buf[c][p][SWZ(j)];
        float2 a1 = cmul(buf[c][p][SWZ(j + 64)],  w1);
        float2 a2 = cmul(buf[c][p][SWZ(j + 128)], w2);
        float2 a3 = cmul(buf[c][p][SWZ(j + 192)], w3);
        float2 s0 = cadd(a0, a2), d0 = csub(a0, a2);
        float2 s1 = cadd(a1, a3), d1 = csub(a1, a3);
        int bse = ((j >> (2 * st)) << (2 * st + 2)) + r;
        buf[c][p ^ 1][SWZ(bse)]          = cadd(s0, s1);
        buf[c][p ^ 1][SWZ(bse + Ns)]     = make_float2(d0.x + d1.y, d0.y - d1.x);
        buf[c][p ^ 1][SWZ(bse + 2 * Ns)] = csub(s0, s1);
        buf[c][p ^ 1][SWZ(bse + 3 * Ns)] = make_float2(d0.x - d1.y, d0.y + d1.x);
        p ^= 1;
        __syncthreads();
    }

    // unpack 256-pt complex -> 512-pt rfft bins
#pragma unroll
    for (int q = 0; q < 4; q++) {
        int k = j + 64 * q;
        float2 Zk = buf[c][p][SWZ(k)];
        int km = (256 - k) & 255;
        float2 Zm = buf[c][p][SWZ(km)];
        float Ex = 0.5f * (Zk.x + Zm.x), Ey = 0.5f * (Zk.y - Zm.y);
        float Dx = 0.5f * (Zk.x - Zm.x), Dy = 0.5f * (Zk.y + Zm.y);
        float Ox = Dy, Oy = -Dx;  // -i * D
        float sn, cs;
        __sincosf(CW * (float)k, &sn, &cs);
        sX[c][k] = make_float2(Ex + (Ox * cs - Oy * sn),
                               Ey + (Ox * sn + Oy * cs));
    }
    if (j == 0) {
        float2 Z0 = buf[c][p][SWZ(0)];
        sX[c][256] = make_float2(Z0.x - Z0.y, 0.0f);
    }
    __syncthreads();

    // beamform: Y[s][k] = sum_c conj(w)[s][k][c] * X[c][k]
    float2* Yout = g_Y + ((size_t)(b * NS) * NFRM + t) * NF;
    for (int item = tid; item < NS * NF; item += 128) {
        int s = (item >= NF);
        int k = item - s * NF;
        float2 w0 = g_wc[(s * NF + k) * 2];
        float2 w1 = g_wc[(s * NF + k) * 2 + 1];
        float2 X0 = sX[0][k], X1 = sX[1][k];
        float yr = w0.x * X0.x - w0.y * X0.y + w1.x * X1.x - w1.y * X1.y;
        float yi = w0.x * X0.y + w0.y * X0.x + w1.x * X1.y + w1.y * X1.x;
        Yout[(size_t)s * NFRM * NF + k] = make_float2(yr, yi);
    }
}

// ---------------- transpose Y [t][f] -> planar output [f][t] per (b,s) ----------------
__global__ void k_transpose(float* __restrict__ reOut, float* __restrict__ imOut,
                            unsigned long long planeCap) {
    __shared__ float2 tile[32][33];
    int bs = blockIdx.z;
    int f0 = blockIdx.x << 5, t0 = blockIdx.y << 5;
    const float2* src = g_Y + (size_t)bs * NFRM * NF;
#pragma unroll
    for (int i = 0; i < 4; i++) {
        int tt = t0 + threadIdx.y + i * 8, ff = f0 + threadIdx.x;
        if (tt < NFRM && ff < NF)
            tile[threadIdx.y + i * 8][threadIdx.x] = src[(size_t)tt * NF + ff];
    }
    __syncthreads();
    size_t dbase = (size_t)bs * NF * NFRM;
#pragma unroll
    for (int i = 0; i < 4; i++) {
        int ff = f0 + threadIdx.y + i * 8, tt = t0 + threadIdx.x;
        if (ff < NF && tt < NFRM) {
            size_t di = dbase + (size_t)ff * NFRM + tt;
            if (di < planeCap) {
                float2 v = tile[threadIdx.x][threadIdx.y + i * 8];
                reOut[di] = v.x;
                if (imOut) imOut[di] = v.y;
            }
        }
    }
}

// ---------------- inverse rfft (radix-4, swizzled, sincosf) + window ----------------
__global__ __launch_bounds__(128) void k_istft() {
    int bt = blockIdx.x;
    int b = bt / NFRM, t = bt - b * NFRM;
    int tid = threadIdx.x;
    int s = tid >> 6, j = tid & 63;

    __shared__ float2 buf[2][2][NHALF];
    __shared__ float2 sX[2][NF];

    const float2* Yin = g_Y + ((size_t)(b * NS + s) * NFRM + t) * NF;
#pragma unroll
    for (int q = 0; q < 4; q++) sX[s][j + 64 * q] = Yin[j + 64 * q];
    if (j == 0) {
        // irfft ignores imag of bins 0 and N/2
        sX[s][0]   = make_float2(Yin[0].x, 0.0f);
        sX[s][256] = make_float2(Yin[256].x, 0.0f);
    }
    __syncthreads();

    // pack -> registers, then stage 0 (inverse, +i) in registers
    float2 z[4];
#pragma unroll
    for (int q = 0; q < 4; q++) {
        int k = j + 64 * q;
        float2 Xk = sX[s][k];
        float2 Xm = sX[s][256 - k];
        float Ex = 0.5f * (Xk.x + Xm.x), Ey = 0.5f * (Xk.y - Xm.y);
        float Dx = 0.5f * (Xk.x - Xm.x), Dy = 0.5f * (Xk.y + Xm.y);
        float sn, cs;
        __sincosf(CW * (float)k, &sn, &cs);      // w = W_512^k
        float Ox = Dx * cs + Dy * sn;            // D * conj(w)
        float Oy = Dy * cs - Dx * sn;
        z[q] = make_float2(Ex - Oy, Ey + Ox);    // E + i*O
    }
    {
        float2 s0 = cadd(z[0], z[2]), d0 = csub(z[0], z[2]);
        float2 s1 = cadd(z[1], z[3]), d1 = csub(z[1], z[3]);
        buf[s][0][SWZ(4 * j + 0)] = cadd(s0, s1);
        buf[s][0][SWZ(4 * j + 1)] = make_float2(d0.x - d1.y, d0.y + d1.x);  // d0 + i d1
        buf[s][0][SWZ(4 * j + 2)] = csub(s0, s1);
        buf[s][0][SWZ(4 * j + 3)] = make_float2(d0.x + d1.y, d0.y - d1.x);  // d0 - i d1
    }
    __syncthreads();

    int p = 0;
#pragma unroll
    for (int st = 1; st < 3; st++) {
        int Ns = 1 << (2 * st);
        int r = j & (Ns - 1);
        int tb = r << (7 - 2 * st);
        float sn, cs;
        __sincosf(-CW * (float)tb, &sn, &cs);    // conj twiddle: exp(+i 2pi tb/512)
        float2 w1 = make_float2(cs, sn);
        float2 w2 = cmul(w1, w1);
        float2 w3 = cmul(w2, w1);
        float2 a0 = buf[s][p][SWZ(j)];
        float2 a1 = cmul(buf[s][p][SWZ(j + 64)],  w1);
        float2 a2 = cmul(buf[s][p][SWZ(j + 128)], w2);
        float2 a3 = cmul(buf[s][p][SWZ(j + 192)], w3);
        float2 s0 = cadd(a0, a2), d0 = csub(a0, a2);
        float2 s1 = cadd(a1, a3), d1 = csub(a1, a3);
        int bse = ((j >> (2 * st)) << (2 * st + 2)) + r;
        buf[s][p ^ 1][SWZ(bse)]          = cadd(s0, s1);
        buf[s][p ^ 1][SWZ(bse + Ns)]     = make_float2(d0.x - d1.y, d0.y + d1.x);
        buf[s][p ^ 1][SWZ(bse + 2 * Ns)] = csub(s0, s1);
        buf[s][p ^ 1][SWZ(bse + 3 * Ns)] = make_float2(d0.x + d1.y, d0.y - d1.x);
        p ^= 1;
        __syncthreads();
    }

    // stage 3 (Ns=64): outputs land at j + 64q -> write gmem directly
    {
        int tb = j << 1;
        float sn, cs;
        __sincosf(-CW * (float)tb, &sn, &cs);
        float2 w1 = make_float2(cs, sn);
        float2 w2 = cmul(w1, w1);
        float2 w3 = cmul(w2, w1);
        float2 a0 = buf[s][p][SWZ(j)];
        float2 a1 = cmul(buf[s][p][SWZ(j + 64)],  w1);
        float2 a2 = cmul(buf[s][p][SWZ(j + 128)], w2);
        float2 a3 = cmul(buf[s][p][SWZ(j + 192)], w3);
        float2 s0 = cadd(a0, a2), d0 = csub(a0, a2);
        float2 s1 = cadd(a1, a3), d1 = csub(a1, a3);
        float2 cc[4];
        cc[0] = cadd(s0, s1);
        cc[1] = make_float2(d0.x - d1.y, d0.y + d1.x);
        cc[2] = csub(s0, s1);
        cc[3] = make_float2(d0.x + d1.y, d0.y - d1.x);

        float2* fout = g_frames2 + ((size_t)(b * NS + s) * NFRM + t) * NHALF;
        const float sc = 1.0f / 256.0f;
#pragma unroll
        for (int q = 0; q < 4; q++) {
            int k = j + 64 * q;
            fout[k] = make_float2(cc[q].x * sc * g_win[2 * k],
                                  cc[q].y * sc * g_win[2 * k + 1]);
        }
    }
}

// ---------------- overlap-add (vectorized, 2 samples/thread) ----------------
__global__ void k_combine(float* __restrict__ yt, unsigned long long cap) {
    int idx = blockIdx.x * blockDim.x + threadIdx.x;
    const int half = NT / 2;
    if (idx >= NB * NS * half) return;
    int bs = idx / half;
    int mo = (idx - bs * half) * 2;
    int m = mo + PADN;
    int klo = m - 384;
    klo = (klo < 0) ? 0 : (klo >> 7);
    int khi = m >> 7;
    if (khi > NFRM - 1) khi = NFRM - 1;
    const float2* fr2 = g_frames2 + (size_t)bs * NFRM * NHALF;
    float y0 = 0.0f, y1 = 0.0f, e0 = 0.0f, e1 = 0.0f;
    for (int k = klo; k <= khi; k++) {
        int r = m - (k << 7);   // even, <= 510
        float2 v = fr2[(size_t)k * NHALF + (r >> 1)];
        y0 += v.x; y1 += v.y;
        e0 += g_win2[r]; e1 += g_win2[r + 1];
    }
    float2 out = make_float2(y0 / e0, y1 / e1);
    size_t i0 = (size_t)(bs * 2) * NT + mo;
    size_t i1 = (size_t)(bs * 2 + 1) * NT + mo;
    if (i0 + 1 < cap) *(float2*)(yt + i0) = out;
    if (i1 + 1 < cap) *(float2*)(yt + i1) = out;
}

// ---------------- launcher ----------------
extern "C" void kernel_launch(void* const* d_in, const int* in_sizes, int n_in,
                              void* d_out, int out_size) {
    const float* x = 0; const float* small[2] = {0, 0}; int nsmall = 0;
    for (int i = 0; i < n_in && i < 3; i++) {
        if (in_sizes[i] > 1000000) x = (const float*)d_in[i];
        else if (nsmall < 2) small[nsmall++] = (const float*)d_in[i];
    }
    const float* sr = small[0] ? small[0] : (const float*)d_in[1];
    const float* si = small[1] ? small[1] : (const float*)d_in[2];
    if (!x) x = (const float*)d_in[0];

    size_t osz = (size_t)out_size;
    float* base = (float*)d_out;

    float* yt = 0;  unsigned long long ytCap = 0;
    float* re = 0;  float* im = 0;  unsigned long long planeCap = 0;

    if (osz == YT_N + YB_N) {
        yt = base;              ytCap = YT_N;
        re = base + YT_N;       im = base + YT_N + YB_E;   planeCap = YB_E;
    } else if (osz == YT_N + YB_E) {
        yt = base;              ytCap = YT_N;
        re = base + YT_N;       im = 0;                    planeCap = YB_E;
    } else if (osz == YT_N) {
        yt = base;              ytCap = YT_N;
    } else if (osz == YB_N) {
        re = base;              im = base + YB_E;          planeCap = YB_E;
    } else if (osz == YB_E) {
        re = base;              im = 0;                    planeCap = YB_E;
    } else {
        yt = base;              ytCap = (osz < YT_N) ? osz : YT_N;
        if (osz > YT_N) {
            size_t rem = osz - YT_N;
            re = base + YT_N;
            if (rem >= 2 * YB_E) { im = base + YT_N + YB_E; planeCap = YB_E; }
            else                 { im = 0; planeCap = rem; }
        }
    }

    k_init<<<1, 512>>>(sr, si);
    k_stft<<<NB * NFRM, 128>>>(x);
    if (re) {
        dim3 tg((NF + 31) / 32, (NFRM + 31) / 32, NB * NS);
        k_transpose<<<tg, dim3(32, 8)>>>(re, im, planeCap);
    }
    if (yt) {
        k_istft<<<NB * NFRM, 128>>>();
        k_combine<<<(NB * NS * (NT / 2) + 255) / 256, 256>>>(yt, ytCap);
    }
}

// round 7
// speedup vs baseline: 2.2115x; 1.0899x over previous
#include <cuda_runtime.h>
#include <math.h>

#define NB   16
#define NC   2
#define NS   2
#define NF   257
#define NFFT 512
#define NHALF 256
#define HOP  128
#define PADN 256
#define NFRM 2501
#define NT   320000

#define YT_N ((size_t)NB * NS * NC * NT)          // 20,480,000 floats (y_time)
#define YB_E ((size_t)NB * NS * NF * NFRM)        // 20,568,224 complex elements
#define YB_N (YB_E * 2)                           // 41,136,448 floats (re+im)

// bank-conflict swizzle for the FFT smem buffer: flip bits [2:3] with bits [4:5]
#define SWZ(k) ((k) ^ (((k) >> 2) & 12))

#define CW (-0.012271846303085129f)   // -2*pi/512

// ---------------- device scratch ----------------
__device__ float2 g_Y[(size_t)NB * NS * NFRM * NF];          // beamformed STFT [b][s][t][f]
__device__ float2 g_frames2[(size_t)NB * NS * NFRM * NHALF]; // windowed irfft frames (pairs)
__device__ float2 g_wc[NS * NF * NC];                        // conj(w)
__device__ float  g_win[NFFT];
__device__ float  g_win2[NFFT];

__device__ __forceinline__ float2 cadd(float2 a, float2 b) { return make_float2(a.x + b.x, a.y + b.y); }
__device__ __forceinline__ float2 csub(float2 a, float2 b) { return make_float2(a.x - b.x, a.y - b.y); }
__device__ __forceinline__ float2 cmul(float2 a, float2 w) {
    return make_float2(a.x * w.x - a.y * w.y, a.x * w.y + a.y * w.x);
}

// ---------------- init ----------------
__global__ void k_init(const float* __restrict__ sr, const float* __restrict__ si) {
    int tid = threadIdx.x;  // 512 threads
    {
        double ang = 2.0 * M_PI * (double)tid / 512.0;
        float w = (float)(0.5 - 0.5 * cos(ang));
        g_win[tid] = w;
        g_win2[tid] = w * w;
    }
    for (int i = tid; i < NS * NF; i += 512) {
        int base = i * 2;
        float a0r = sr[base], a0i = si[base];
        float a1r = sr[base + 1], a1i = si[base + 1];
        float den = a0r * a0r + a0i * a0i + a1r * a1r + a1i * a1i;
        float inv = 1.0f / den;
        g_wc[base]     = make_float2(a0r * inv, -a0i * inv);
        g_wc[base + 1] = make_float2(a1r * inv, -a1i * inv);
    }
}

__device__ __forceinline__ int reflect_idx(int i) {
    i = (i < 0) ? -i : i;
    return (i >= NT) ? (2 * NT - 2 - i) : i;
}

// ============ FUSED: STFT + beamform + inverse rfft + window; one block/(b,t) ============
__global__ __launch_bounds__(128) void k_fused(const float* __restrict__ x) {
    int bt = blockIdx.x;
    int b = bt / NFRM, t = bt - b * NFRM;
    int tid = threadIdx.x;
    int c = tid >> 6, j = tid & 63;   // role index (channel for fwd, steer for inv)

    __shared__ float2 buf[2][2][NHALF];
    __shared__ float2 sX[2][NF];
    __shared__ float2 sY[2][NF];

    // ---- load + window + pack ----
    const float* xin = x + (size_t)(b * NC + c) * NT;
    int base = t * HOP - PADN;
    float2 v[4];
    if (t >= 2 && t <= 2498) {  // interior: aligned float2 fast path
        const float2* x2 = (const float2*)(xin + base);
#pragma unroll
        for (int q = 0; q < 4; q++) {
            int k = j + 64 * q;
            float2 xx = x2[k];
            v[q] = make_float2(xx.x * g_win[2 * k], xx.y * g_win[2 * k + 1]);
        }
    } else {
#pragma unroll
        for (int q = 0; q < 4; q++) {
            int k = j + 64 * q;
            int i0 = base + 2 * k;
            v[q] = make_float2(xin[reflect_idx(i0)] * g_win[2 * k],
                               xin[reflect_idx(i0 + 1)] * g_win[2 * k + 1]);
        }
    }

    // ---- forward radix-4 Stockham, stage 0 in registers ----
    {
        float2 s0 = cadd(v[0], v[2]), d0 = csub(v[0], v[2]);
        float2 s1 = cadd(v[1], v[3]), d1 = csub(v[1], v[3]);
        buf[c][0][SWZ(4 * j + 0)] = cadd(s0, s1);
        buf[c][0][SWZ(4 * j + 1)] = make_float2(d0.x + d1.y, d0.y - d1.x);  // d0 - i d1
        buf[c][0][SWZ(4 * j + 2)] = csub(s0, s1);
        buf[c][0][SWZ(4 * j + 3)] = make_float2(d0.x - d1.y, d0.y + d1.x);  // d0 + i d1
    }
    __syncthreads();

    int p = 0;
#pragma unroll
    for (int st = 1; st < 4; st++) {
        int Ns = 1 << (2 * st);
        int r = j & (Ns - 1);
        int tb = r << (7 - 2 * st);
        float sn, cs;
        __sincosf(CW * (float)tb, &sn, &cs);
        float2 w1 = make_float2(cs, sn);
        float2 w2 = cmul(w1, w1);
        float2 w3 = cmul(w2, w1);
        float2 a0 = buf[c][p][SWZ(j)];
        float2 a1 = cmul(buf[c][p][SWZ(j + 64)],  w1);
        float2 a2 = cmul(buf[c][p][SWZ(j + 128)], w2);
        float2 a3 = cmul(buf[c][p][SWZ(j + 192)], w3);
        float2 s0 = cadd(a0, a2), d0 = csub(a0, a2);
        float2 s1 = cadd(a1, a3), d1 = csub(a1, a3);
        int bse = ((j >> (2 * st)) << (2 * st + 2)) + r;
        buf[c][p ^ 1][SWZ(bse)]          = cadd(s0, s1);
        buf[c][p ^ 1][SWZ(bse + Ns)]     = make_float2(d0.x + d1.y, d0.y - d1.x);
        buf[c][p ^ 1][SWZ(bse + 2 * Ns)] = csub(s0, s1);
        buf[c][p ^ 1][SWZ(bse + 3 * Ns)] = make_float2(d0.x - d1.y, d0.y + d1.x);
        p ^= 1;
        __syncthreads();
    }

    // ---- unpack 256-pt complex -> 512-pt rfft bins ----
#pragma unroll
    for (int q = 0; q < 4; q++) {
        int k = j + 64 * q;
        float2 Zk = buf[c][p][SWZ(k)];
        int km = (256 - k) & 255;
        float2 Zm = buf[c][p][SWZ(km)];
        float Ex = 0.5f * (Zk.x + Zm.x), Ey = 0.5f * (Zk.y - Zm.y);
        float Dx = 0.5f * (Zk.x - Zm.x), Dy = 0.5f * (Zk.y + Zm.y);
        float Ox = Dy, Oy = -Dx;  // -i * D
        float sn, cs;
        __sincosf(CW * (float)k, &sn, &cs);
        sX[c][k] = make_float2(Ex + (Ox * cs - Oy * sn),
                               Ey + (Ox * sn + Oy * cs));
    }
    if (j == 0) {
        float2 Z0 = buf[c][p][SWZ(0)];
        sX[c][256] = make_float2(Z0.x - Z0.y, 0.0f);
    }
    __syncthreads();

    // ---- beamform: write g_Y (for output) AND sY (for the inverse) ----
    float2* Yout = g_Y + ((size_t)(b * NS) * NFRM + t) * NF;
    for (int item = tid; item < NS * NF; item += 128) {
        int s = (item >= NF);
        int k = item - s * NF;
        float2 w0 = g_wc[(s * NF + k) * 2];
        float2 w1 = g_wc[(s * NF + k) * 2 + 1];
        float2 X0 = sX[0][k], X1 = sX[1][k];
        float2 y = make_float2(
            w0.x * X0.x - w0.y * X0.y + w1.x * X1.x - w1.y * X1.y,
            w0.x * X0.y + w0.y * X0.x + w1.x * X1.y + w1.y * X1.x);
        sY[s][k] = y;
        Yout[(size_t)s * NFRM * NF + k] = y;
    }
    __syncthreads();

    // ---- inverse rfft from sY (role index now = steering s) ----
    int s = c;
    float2 z[4];
#pragma unroll
    for (int q = 0; q < 4; q++) {
        int k = j + 64 * q;
        float2 Xk = sY[s][k];
        float2 Xm = sY[s][256 - k];
        if (k == 0) { Xk.y = 0.0f; Xm.y = 0.0f; }  // irfft drops imag of bins 0, 256
        float Ex = 0.5f * (Xk.x + Xm.x), Ey = 0.5f * (Xk.y - Xm.y);
        float Dx = 0.5f * (Xk.x - Xm.x), Dy = 0.5f * (Xk.y + Xm.y);
        float sn, cs;
        __sincosf(CW * (float)k, &sn, &cs);      // w = W_512^k
        float Ox = Dx * cs + Dy * sn;            // D * conj(w)
        float Oy = Dy * cs - Dx * sn;
        z[q] = make_float2(Ex - Oy, Ey + Ox);    // E + i*O
    }
    {
        float2 s0 = cadd(z[0], z[2]), d0 = csub(z[0], z[2]);
        float2 s1 = cadd(z[1], z[3]), d1 = csub(z[1], z[3]);
        buf[s][0][SWZ(4 * j + 0)] = cadd(s0, s1);
        buf[s][0][SWZ(4 * j + 1)] = make_float2(d0.x - d1.y, d0.y + d1.x);  // d0 + i d1
        buf[s][0][SWZ(4 * j + 2)] = csub(s0, s1);
        buf[s][0][SWZ(4 * j + 3)] = make_float2(d0.x + d1.y, d0.y - d1.x);  // d0 - i d1
    }
    __syncthreads();

    p = 0;
#pragma unroll
    for (int st = 1; st < 3; st++) {
        int Ns = 1 << (2 * st);
        int r = j & (Ns - 1);
        int tb = r << (7 - 2 * st);
        float sn, cs;
        __sincosf(-CW * (float)tb, &sn, &cs);    // conj twiddle
        float2 w1 = make_float2(cs, sn);
        float2 w2 = cmul(w1, w1);
        float2 w3 = cmul(w2, w1);
        float2 a0 = buf[s][p][SWZ(j)];
        float2 a1 = cmul(buf[s][p][SWZ(j + 64)],  w1);
        float2 a2 = cmul(buf[s][p][SWZ(j + 128)], w2);
        float2 a3 = cmul(buf[s][p][SWZ(j + 192)], w3);
        float2 s0 = cadd(a0, a2), d0 = csub(a0, a2);
        float2 s1 = cadd(a1, a3), d1 = csub(a1, a3);
        int bse = ((j >> (2 * st)) << (2 * st + 2)) + r;
        buf[s][p ^ 1][SWZ(bse)]          = cadd(s0, s1);
        buf[s][p ^ 1][SWZ(bse + Ns)]     = make_float2(d0.x - d1.y, d0.y + d1.x);
        buf[s][p ^ 1][SWZ(bse + 2 * Ns)] = csub(s0, s1);
        buf[s][p ^ 1][SWZ(bse + 3 * Ns)] = make_float2(d0.x + d1.y, d0.y - d1.x);
        p ^= 1;
        __syncthreads();
    }

    // stage 3 (Ns=64): outputs land at j + 64q -> write gmem directly
    {
        int tb = j << 1;
        float sn, cs;
        __sincosf(-CW * (float)tb, &sn, &cs);
        float2 w1 = make_float2(cs, sn);
        float2 w2 = cmul(w1, w1);
        float2 w3 = cmul(w2, w1);
        float2 a0 = buf[s][p][SWZ(j)];
        float2 a1 = cmul(buf[s][p][SWZ(j + 64)],  w1);
        float2 a2 = cmul(buf[s][p][SWZ(j + 128)], w2);
        float2 a3 = cmul(buf[s][p][SWZ(j + 192)], w3);
        float2 s0 = cadd(a0, a2), d0 = csub(a0, a2);
        float2 s1 = cadd(a1, a3), d1 = csub(a1, a3);
        float2 cc[4];
        cc[0] = cadd(s0, s1);
        cc[1] = make_float2(d0.x - d1.y, d0.y + d1.x);
        cc[2] = csub(s0, s1);
        cc[3] = make_float2(d0.x + d1.y, d0.y - d1.x);

        float2* fout = g_frames2 + ((size_t)(b * NS + s) * NFRM + t) * NHALF;
        const float sc = 1.0f / 256.0f;
#pragma unroll
        for (int q = 0; q < 4; q++) {
            int k = j + 64 * q;
            fout[k] = make_float2(cc[q].x * sc * g_win[2 * k],
                                  cc[q].y * sc * g_win[2 * k + 1]);
        }
    }
}

// ---------------- transpose Y [t][f] -> planar output [f][t] per (b,s) ----------------
__global__ void k_transpose(float* __restrict__ reOut, float* __restrict__ imOut,
                            unsigned long long planeCap) {
    __shared__ float2 tile[32][33];
    int bs = blockIdx.z;
    int f0 = blockIdx.x << 5, t0 = blockIdx.y << 5;
    const float2* src = g_Y + (size_t)bs * NFRM * NF;
#pragma unroll
    for (int i = 0; i < 4; i++) {
        int tt = t0 + threadIdx.y + i * 8, ff = f0 + threadIdx.x;
        if (tt < NFRM && ff < NF)
            tile[threadIdx.y + i * 8][threadIdx.x] = src[(size_t)tt * NF + ff];
    }
    __syncthreads();
    size_t dbase = (size_t)bs * NF * NFRM;
#pragma unroll
    for (int i = 0; i < 4; i++) {
        int ff = f0 + threadIdx.y + i * 8, tt = t0 + threadIdx.x;
        if (ff < NF && tt < NFRM) {
            size_t di = dbase + (size_t)ff * NFRM + tt;
            if (di < planeCap) {
                float2 v = tile[threadIdx.x][threadIdx.y + i * 8];
                reOut[di] = v.x;
                if (imOut) imOut[di] = v.y;
            }
        }
    }
}

// ---------------- overlap-add (vectorized, 2 samples/thread) ----------------
__global__ void k_combine(float* __restrict__ yt, unsigned long long cap) {
    int idx = blockIdx.x * blockDim.x + threadIdx.x;
    const int half = NT / 2;
    if (idx >= NB * NS * half) return;
    int bs = idx / half;
    int mo = (idx - bs * half) * 2;
    int m = mo + PADN;
    int klo = m - 384;
    klo = (klo < 0) ? 0 : (klo >> 7);
    int khi = m >> 7;
    if (khi > NFRM - 1) khi = NFRM - 1;
    const float2* fr2 = g_frames2 + (size_t)bs * NFRM * NHALF;
    float y0 = 0.0f, y1 = 0.0f, e0 = 0.0f, e1 = 0.0f;
    for (int k = klo; k <= khi; k++) {
        int r = m - (k << 7);   // even, <= 510
        float2 v = fr2[(size_t)k * NHALF + (r >> 1)];
        y0 += v.x; y1 += v.y;
        e0 += g_win2[r]; e1 += g_win2[r + 1];
    }
    float2 out = make_float2(y0 / e0, y1 / e1);
    size_t i0 = (size_t)(bs * 2) * NT + mo;
    size_t i1 = (size_t)(bs * 2 + 1) * NT + mo;
    if (i0 + 1 < cap) *(float2*)(yt + i0) = out;
    if (i1 + 1 < cap) *(float2*)(yt + i1) = out;
}

// ---------------- launcher ----------------
extern "C" void kernel_launch(void* const* d_in, const int* in_sizes, int n_in,
                              void* d_out, int out_size) {
    const float* x = 0; const float* small[2] = {0, 0}; int nsmall = 0;
    for (int i = 0; i < n_in && i < 3; i++) {
        if (in_sizes[i] > 1000000) x = (const float*)d_in[i];
        else if (nsmall < 2) small[nsmall++] = (const float*)d_in[i];
    }
    const float* sr = small[0] ? small[0] : (const float*)d_in[1];
    const float* si = small[1] ? small[1] : (const float*)d_in[2];
    if (!x) x = (const float*)d_in[0];

    size_t osz = (size_t)out_size;
    float* base = (float*)d_out;

    float* yt = 0;  unsigned long long ytCap = 0;
    float* re = 0;  float* im = 0;  unsigned long long planeCap = 0;

    if (osz == YT_N + YB_N) {
        yt = base;              ytCap = YT_N;
        re = base + YT_N;       im = base + YT_N + YB_E;   planeCap = YB_E;
    } else if (osz == YT_N + YB_E) {
        yt = base;              ytCap = YT_N;
        re = base + YT_N;       im = 0;                    planeCap = YB_E;
    } else if (osz == YT_N) {
        yt = base;              ytCap = YT_N;
    } else if (osz == YB_N) {
        re = base;              im = base + YB_E;          planeCap = YB_E;
    } else if (osz == YB_E) {
        re = base;              im = 0;                    planeCap = YB_E;
    } else {
        yt = base;              ytCap = (osz < YT_N) ? osz : YT_N;
        if (osz > YT_N) {
            size_t rem = osz - YT_N;
            re = base + YT_N;
            if (rem >= 2 * YB_E) { im = base + YT_N + YB_E; planeCap = YB_E; }
            else                 { im = 0; planeCap = rem; }
        }
    }

    k_init<<<1, 512>>>(sr, si);
    k_fused<<<NB * NFRM, 128>>>(x);
    if (re) {
        dim3 tg((NF + 31) / 32, (NFRM + 31) / 32, NB * NS);
        k_transpose<<<tg, dim3(32, 8)>>>(re, im, planeCap);
    }
    if (yt) {
        k_combine<<<(NB * NS * (NT / 2) + 255) / 256, 256>>>(yt, ytCap);
    }
}